// round 3
// baseline (speedup 1.0000x reference)
#include <cuda_runtime.h>
#include <cstdint>

// RoIPooling (TF2 crop_and_resize bilinear, POOL=7)
// feature_map: (1, 256, 256, 512) float32 NHWC
// proposals:   (512, 4) int32  [x, y, w, h]
// output:      (512, 7, 7, 512) float32
//
// R3: One CTA per (proposal, py): 3584 blocks x 128 threads, thread owns a
// channel-quad. Phase 1 issues ALL 28 corner float4 loads into register
// arrays (per-warp MLP ~28, ~14KB in flight) before phase 2 blends and
// streaming-stores. Trades occupancy (high regcount) for memory-level
// parallelism — the R2 profile showed exposed latency, no saturated pipe.

#define POOL 7
#define FM_H 256
#define FM_W 256
#define FM_C 512
#define NPROP 512
#define C4 (FM_C / 4)

__global__ __launch_bounds__(128)
void roi_pool_kernel(const float* __restrict__ fm,
                     const int*   __restrict__ props,
                     float*       __restrict__ out)
{
    const int bid = blockIdx.x;           // 0 .. 3583
    const int n   = bid / POOL;
    const int py  = bid - n * POOL;

    const int4 box = reinterpret_cast<const int4*>(props)[n];
    const int bx = box.x, by = box.y, bw = box.z, bh = box.w;

    // --- y axis coords (match reference float32 math) ---
    const float hf = (float)bh;
    float sy = ((float)py + 0.5f) * (hf / (float)POOL) - 0.5f;
    sy = fminf(fmaxf(sy, 0.0f), hf - 1.0f);
    const int   iy0 = (int)floorf(sy);
    const int   iy1 = min(iy0 + 1, bh - 1);
    const float fy  = sy - (float)iy0;
    const float ofy = 1.0f - fy;

    const float4* __restrict__ row0 =
        reinterpret_cast<const float4*>(fm + ((size_t)(by + iy0) * FM_W + bx) * FM_C);
    const float4* __restrict__ row1 =
        reinterpret_cast<const float4*>(fm + ((size_t)(by + iy1) * FM_W + bx) * FM_C);

    const int c = threadIdx.x;            // float4 (channel-quad) index 0..127
    const float wf = (float)bw;
    const float xscale = wf / (float)POOL;

    // --- phase 0: x coords for all 7 cells ---
    int   ix0[POOL], ix1[POOL];
    float fx[POOL];
    #pragma unroll
    for (int px = 0; px < POOL; ++px) {
        float sx = ((float)px + 0.5f) * xscale - 0.5f;
        sx = fminf(fmaxf(sx, 0.0f), wf - 1.0f);
        ix0[px] = (int)floorf(sx);
        ix1[px] = min(ix0[px] + 1, bw - 1);
        fx[px]  = sx - (float)ix0[px];
    }

    // --- phase 1: issue all 28 corner loads (batched, high MLP) ---
    float4 A[POOL], B[POOL], G[POOL], D[POOL];
    #pragma unroll
    for (int px = 0; px < POOL; ++px) {
        A[px] = row0[ix0[px] * C4 + c];
        B[px] = row0[ix1[px] * C4 + c];
        G[px] = row1[ix0[px] * C4 + c];
        D[px] = row1[ix1[px] * C4 + c];
    }

    // --- phase 2: blend + streaming store ---
    float4* __restrict__ orow =
        reinterpret_cast<float4*>(out + ((size_t)n * (POOL * POOL) + (size_t)py * POOL) * FM_C);

    #pragma unroll
    for (int px = 0; px < POOL; ++px) {
        const float f  = fx[px];
        const float of = 1.0f - f;
        float4 o;
        o.x = (A[px].x * of + B[px].x * f) * ofy + (G[px].x * of + D[px].x * f) * fy;
        o.y = (A[px].y * of + B[px].y * f) * ofy + (G[px].y * of + D[px].y * f) * fy;
        o.z = (A[px].z * of + B[px].z * f) * ofy + (G[px].z * of + D[px].z * f) * fy;
        o.w = (A[px].w * of + B[px].w * f) * ofy + (G[px].w * of + D[px].w * f) * fy;
        __stcs(&orow[px * C4 + c], o);
    }
}

extern "C" void kernel_launch(void* const* d_in, const int* in_sizes, int n_in,
                              void* d_out, int out_size)
{
    const float* fm    = (const float*)d_in[0];
    const int*   props = (const int*)d_in[1];
    float*       out   = (float*)d_out;

    const int blocks = NPROP * POOL;      // 3584
    roi_pool_kernel<<<blocks, 128>>>(fm, props, out);
}